// round 9
// baseline (speedup 1.0000x reference)
#include <cuda_runtime.h>
#include <cuda_bf16.h>
#include <math.h>

// Problem constants (fixed by the dataset)
constexpr int NN   = 50000;   // nodes
constexpr int NE   = 800000;  // edges
constexpr int F_IN = 128;
constexpr int D1   = 256;
constexpr int D2   = 128;
constexpr int KC   = 32;      // clusters

// ---------------- scratch (static device globals; no allocation) -------------
__device__ float g_xw[(size_t)NN * D1];     // features @ W1
__device__ float g_H[(size_t)NN * D1];      // GCN output (+b1)
__device__ float g_abs[(size_t)NN * D2];    // tanh(H@fc1_W+fc1_b)
__device__ float g_S[(size_t)NN * KC];      // softmax assignments
__device__ float g_LS[(size_t)NN * KC];     // L @ S
__device__ int   g_deg1[NN];                // in-degree + 1 (GCN norm)
__device__ int   g_deg2[NN];                // out-degree (Laplacian)
__device__ float g_dinv1[NN];
__device__ float g_dinv2[NN];
__device__ float g_newadj[KC * KC];
__device__ float g_hsum[D1];

// ---------------- init: degrees, accumulators --------------------------------
__global__ void k_init() {
    int i = blockIdx.x * blockDim.x + threadIdx.x;
    if (i < NN) { g_deg1[i] = 1; g_deg2[i] = 0; }
    if (i < KC * KC) g_newadj[i] = 0.f;
    if (i < D1) g_hsum[i] = 0.f;
}

__global__ void k_count(const int* __restrict__ row,
                        const int* __restrict__ col) {
    int e = blockIdx.x * blockDim.x + threadIdx.x;
    if (e >= NE) return;
    atomicAdd(&g_deg1[col[e]], 1);
    atomicAdd(&g_deg2[row[e]], 1);
}

__global__ void k_dinv() {
    int i = blockIdx.x * blockDim.x + threadIdx.x;
    if (i >= NN) return;
    g_dinv1[i] = rsqrtf((float)g_deg1[i]);              // deg1 >= 1 always
    int d2 = g_deg2[i];
    g_dinv2[i] = d2 > 0 ? rsqrtf((float)d2) : 0.f;
}

// ---------------- tiled fp32 GEMM ---------------------------------------------
// MODE 0: g_xw  = A_param @ B          (A = features, B = W1)      [NN,128]@[128,256]
// MODE 1: g_abs = tanh(g_H @ B + bias) (B = fc1_W, bias = fc1_b)   [NN,256]@[256,128]
// BM=BN=64, BK=16, 256 threads, 4x4 per thread. All scratch via device symbols.
template<int MODE>
__global__ void k_gemm(const float* __restrict__ Aparam,
                       const float* __restrict__ B,
                       const float* __restrict__ bias,
                       int M, int N, int K) {
    const float* A = (MODE == 0) ? Aparam : g_H;
    float*       C = (MODE == 0) ? g_xw   : g_abs;
    __shared__ float As[16][64];
    __shared__ float Bs[16][64 + 4];
    const int tid = threadIdx.x;
    const int tx = tid & 15, ty = tid >> 4;
    const int rowBase = blockIdx.y * 64, colBase = blockIdx.x * 64;
    float acc[4][4] = {};
    for (int k0 = 0; k0 < K; k0 += 16) {
        #pragma unroll
        for (int i = 0; i < 4; i++) {
            int idx = tid + i * 256;
            int m = idx >> 4, k = idx & 15;
            int r = rowBase + m;
            As[k][m] = (r < M) ? A[(size_t)r * K + k0 + k] : 0.f;
        }
        #pragma unroll
        for (int i = 0; i < 4; i++) {
            int idx = tid + i * 256;
            int k = idx >> 6, n = idx & 63;
            Bs[k][n] = B[(size_t)(k0 + k) * N + colBase + n];
        }
        __syncthreads();
        #pragma unroll
        for (int k = 0; k < 16; k++) {
            float a[4], b[4];
            #pragma unroll
            for (int i = 0; i < 4; i++) a[i] = As[k][ty * 4 + i];
            #pragma unroll
            for (int j = 0; j < 4; j++) b[j] = Bs[k][tx * 4 + j];
            #pragma unroll
            for (int i = 0; i < 4; i++)
                #pragma unroll
                for (int j = 0; j < 4; j++)
                    acc[i][j] = fmaf(a[i], b[j], acc[i][j]);
        }
        __syncthreads();
    }
    #pragma unroll
    for (int i = 0; i < 4; i++) {
        int r = rowBase + ty * 4 + i;
        if (r >= M) continue;
        #pragma unroll
        for (int j = 0; j < 4; j++) {
            int c = colBase + tx * 4 + j;
            float v = acc[i][j];
            if (MODE == 1) v = tanhf(v + bias[c]);
            C[(size_t)r * N + c] = v;
        }
    }
}

// ---------------- GCN self-loop term: H = dinv1^2 * xw -----------------------
__global__ void k_self() {
    size_t gid = (size_t)blockIdx.x * blockDim.x + threadIdx.x;
    if (gid >= (size_t)NN * D1) return;
    int node = (int)(gid >> 8);                 // D1 = 256 floats per row
    float c = g_dinv1[node]; c *= c;
    g_H[gid] = c * g_xw[gid];
}

// ---------------- GCN edge scatter: H[c] += dinv1[r]*dinv1[c] * xw[r] --------
// One warp per edge; each lane handles 8 columns (stride 32) with scalar REDs.
__global__ void k_scatter1(const int* __restrict__ row,
                           const int* __restrict__ col) {
    int wid  = (blockIdx.x * blockDim.x + threadIdx.x) >> 5;
    int lane = threadIdx.x & 31;
    if (wid >= NE) return;
    int r = row[wid], c = col[wid];
    float coef = g_dinv1[r] * g_dinv1[c];
    const float* src = g_xw + (size_t)r * D1;
    float*       dst = g_H  + (size_t)c * D1;
    #pragma unroll
    for (int q = 0; q < 8; q++) {
        int d = lane + q * 32;
        atomicAdd(dst + d, coef * src[d]);
    }
}

// ---------------- H += b1, and accumulate column sums (for embedding) --------
__global__ void k_addb1(const float* __restrict__ b1) {
    const int d = threadIdx.x;                  // 256 threads = one per column
    const int r0 = blockIdx.x * 128;
    const int r1 = min(r0 + 128, NN);
    const float bv = b1[d];
    float part = 0.f;
    for (int n = r0; n < r1; n++) {
        size_t idx = (size_t)n * D1 + d;
        float v = g_H[idx] + bv;
        g_H[idx] = v;
        part += v;
    }
    atomicAdd(&g_hsum[d], part);
}

// ---------------- fused GEMM3 + softmax: S = softmax(abs @ fc2_W + fc2_b) ----
// One warp per row; lane k owns output column k (KC = 32).
__global__ void k_gemm3_softmax(const float* __restrict__ W,
                                const float* __restrict__ b) {
    __shared__ float Wsm[D2 * KC];
    __shared__ float bsm[KC];
    __shared__ float rowsm[8][D2];
    const int tid = threadIdx.x;
    for (int i = tid; i < D2 * KC; i += 256) Wsm[i] = W[i];
    if (tid < KC) bsm[tid] = b[tid];
    __syncthreads();
    const int warp = tid >> 5, lane = tid & 31;
    const int r = blockIdx.x * 8 + warp;
    if (r >= NN) return;
    for (int j = lane; j < D2; j += 32) rowsm[warp][j] = g_abs[(size_t)r * D2 + j];
    __syncwarp();
    float acc = bsm[lane];
    #pragma unroll 8
    for (int j = 0; j < D2; j++) acc = fmaf(rowsm[warp][j], Wsm[j * KC + lane], acc);
    float m = acc;
    #pragma unroll
    for (int o = 16; o; o >>= 1) m = fmaxf(m, __shfl_xor_sync(0xffffffffu, m, o));
    float p = expf(acc - m);
    float s = p;
    #pragma unroll
    for (int o = 16; o; o >>= 1) s += __shfl_xor_sync(0xffffffffu, s, o);
    float v = p / s;
    g_S[(size_t)r * KC + lane]  = v;
    g_LS[(size_t)r * KC + lane] = v;   // LS initialized to I*S
}

// ---------------- Laplacian scatter: LS[r] += -(dinv2[r]*dinv2[c]) * S[c] ----
// One thread per (edge, column): 32 columns per edge, coalesced per warp.
__global__ void k_scatter2(const int* __restrict__ row,
                           const int* __restrict__ col) {
    size_t gid = (size_t)blockIdx.x * blockDim.x + threadIdx.x;
    if (gid >= (size_t)NE * KC) return;
    int e = (int)(gid >> 5), k = (int)(gid & 31);
    int r = row[e], c = col[e];
    float wl = -g_dinv2[r] * g_dinv2[c];
    if (wl == 0.f) return;
    float v = g_S[(size_t)c * KC + k];
    atomicAdd(&g_LS[(size_t)r * KC + k], wl * v);
}

// ---------------- new_adj = S^T @ LS  (32x32 block-local reduction) ----------
__global__ void k_newadj() {
    __shared__ float Ssm[32][33];
    __shared__ float Lsm[32][33];
    const int tid = threadIdx.x;                // 1024 threads
    const int i = tid >> 5, j = tid & 31;
    float acc = 0.f;
    const int base = blockIdx.x * 1024;
    for (int t = 0; t < 32; t++) {
        int nn = base + t * 32 + i;
        float sv = 0.f, lv = 0.f;
        if (nn < NN) {
            sv = g_S[(size_t)nn * KC + j];
            lv = g_LS[(size_t)nn * KC + j];
        }
        Ssm[i][j] = sv;
        Lsm[i][j] = lv;
        __syncthreads();
        #pragma unroll
        for (int n = 0; n < 32; n++) acc = fmaf(Ssm[n][i], Lsm[n][j], acc);
        __syncthreads();
    }
    atomicAdd(&g_newadj[i * KC + j], acc);
}

// ---------------- final: penalty + embedding ---------------------------------
__global__ void k_final(float* __restrict__ out) {
    __shared__ float adj[KC * KC];
    __shared__ float diag[KC];
    const int tid = threadIdx.x;                // 256 threads
    for (int idx = tid; idx < KC * KC; idx += 256) adj[idx] = g_newadj[idx];
    __syncthreads();
    if (tid < KC) {
        float rs = 0.f;
        for (int l = 0; l < KC; l++) rs += fabsf(adj[tid * KC + l]);
        diag[tid] = adj[tid * KC + tid] / fmaxf(rs, 1e-12f);
    }
    __syncthreads();
    if (tid < D1) out[tid] = g_hsum[tid] * (1.0f / (float)KC);
    if (tid == 0) {
        float pp = 0.f;
        for (int jj = 0; jj < KC; jj++) {
            float d = diag[jj];
            pp += (d - 1.f) * (d - 1.f) + (float)(KC - 1) * d * d;
        }
        out[D1] = pp / (float)(KC * KC);
    }
}

// ---------------- host launcher ----------------------------------------------
extern "C" void kernel_launch(void* const* d_in, const int* in_sizes, int n_in,
                              void* d_out, int out_size) {
    const float* features = (const float*)d_in[0];
    const int*   edges    = (const int*)d_in[1];   // int64 -> int32 by harness
    const float* W1       = (const float*)d_in[2];
    const float* b1       = (const float*)d_in[3];
    const float* fc1W     = (const float*)d_in[4];
    const float* fc1b     = (const float*)d_in[5];
    const float* fc2W     = (const float*)d_in[6];
    const float* fc2b     = (const float*)d_in[7];
    float* out = (float*)d_out;

    const int* row = edges;        // edges[0, :]
    const int* col = edges + NE;   // edges[1, :]

    // 1. degree + norm precompute
    k_init<<<(NN + 255) / 256, 256>>>();
    k_count<<<(NE + 255) / 256, 256>>>(row, col);
    k_dinv<<<(NN + 255) / 256, 256>>>();

    // 2. g_xw = features @ W1   [50000,128]@[128,256]
    {
        dim3 grid(D1 / 64, (NN + 63) / 64);
        k_gemm<0><<<grid, 256>>>(features, W1, nullptr, NN, D1, F_IN);
    }

    // 3. GCN aggregation
    {
        size_t total = (size_t)NN * D1;
        k_self<<<(unsigned)((total + 255) / 256), 256>>>();
    }
    {
        size_t threads = (size_t)NE * 32;
        k_scatter1<<<(unsigned)((threads + 255) / 256), 256>>>(row, col);
    }
    k_addb1<<<(NN + 127) / 128, 256>>>(b1);

    // 4. g_abs = tanh(g_H @ fc1_W + fc1_b)   [50000,256]@[256,128]
    {
        dim3 grid(D2 / 64, (NN + 63) / 64);
        k_gemm<1><<<grid, 256>>>(nullptr, fc1W, fc1b, NN, D2, D1);
    }

    // 5. S = softmax(abs @ fc2_W + fc2_b), LS = S
    k_gemm3_softmax<<<(NN + 7) / 8, 256>>>(fc2W, fc2b);

    // 6. LS += scatter of Laplacian off-diagonals
    {
        size_t threads = (size_t)NE * KC;
        k_scatter2<<<(unsigned)((threads + 255) / 256), 256>>>(row, col);
    }

    // 7. new_adj = S^T @ LS
    k_newadj<<<(NN + 1023) / 1024, 1024>>>();

    // 8. outputs
    k_final<<<1, 256>>>(out);
}

// round 10
// speedup vs baseline: 1.1758x; 1.1758x over previous
#include <cuda_runtime.h>
#include <cuda_bf16.h>
#include <math.h>

// Problem constants (fixed by the dataset)
constexpr int NN   = 50000;   // nodes
constexpr int NE   = 800000;  // edges
constexpr int F_IN = 128;
constexpr int D1   = 256;
constexpr int D2   = 128;
constexpr int KC   = 32;      // clusters

// ---------------- scratch (static device globals; no allocation) -------------
__device__ float g_xw[(size_t)NN * D1];     // features @ W1
__device__ float g_H[(size_t)NN * D1];      // GCN output (raw, no +b1)
__device__ float g_abs[(size_t)NN * D2];    // tanh(H@fc1_W+bias2)
__device__ float g_S[(size_t)NN * KC];      // softmax assignments
__device__ float g_LS[(size_t)NN * KC];     // L @ S
__device__ int   g_deg1[NN];                // in-degree + 1 (GCN norm)
__device__ int   g_deg2[NN];                // out-degree (Laplacian)
__device__ float g_dinv1[NN];
__device__ float g_dinv2[NN];
__device__ float g_newadj[KC * KC];
__device__ float g_hsum[D1];
__device__ float g_bias2[D2];               // fc1_b + b1 @ fc1_W

// ---------------- init: degrees, accumulators --------------------------------
__global__ void k_init() {
    int i = blockIdx.x * blockDim.x + threadIdx.x;
    if (i < NN) { g_deg1[i] = 1; g_deg2[i] = 0; }
    if (i < KC * KC) g_newadj[i] = 0.f;
    if (i < D1) g_hsum[i] = 0.f;
}

__global__ void k_count(const int* __restrict__ row,
                        const int* __restrict__ col) {
    int e = blockIdx.x * blockDim.x + threadIdx.x;
    if (e >= NE) return;
    atomicAdd(&g_deg1[col[e]], 1);
    atomicAdd(&g_deg2[row[e]], 1);
}

__global__ void k_dinv() {
    int i = blockIdx.x * blockDim.x + threadIdx.x;
    if (i >= NN) return;
    g_dinv1[i] = rsqrtf((float)g_deg1[i]);              // deg1 >= 1 always
    int d2 = g_deg2[i];
    g_dinv2[i] = d2 > 0 ? rsqrtf((float)d2) : 0.f;
}

// ---------------- bias2[j] = fc1_b[j] + sum_k b1[k] * fc1_W[k][j] ------------
__global__ void k_bias2(const float* __restrict__ b1,
                        const float* __restrict__ fc1W,
                        const float* __restrict__ fc1b) {
    int j = threadIdx.x;                        // 128 threads
    float s = fc1b[j];
    for (int k = 0; k < D1; k++) s = fmaf(b1[k], fc1W[k * D2 + j], s);
    g_bias2[j] = s;
}

// ---------------- 128x128x16 SGEMM, 256 threads, 8x8 microtile ---------------
// MODE 0: g_xw = A@B AND g_H = dinv1[r]^2 * (A@B)   (A=features,B=W1, N=256,K=128)
// MODE 1: g_abs = tanh(g_H@B + g_bias2[col])        (B=fc1_W,       N=128,K=256)
template<int MODE>
__global__ void k_gemm(const float* __restrict__ Aparam,
                       const float* __restrict__ B,
                       int M, int N, int K) {
    const float* A = (MODE == 0) ? Aparam : g_H;
    __shared__ float As[16][136];   // padded: conflict-free transposed stores
    __shared__ float Bs[16][128];
    const int tid = threadIdx.x;
    const int tx = tid & 15, ty = tid >> 4;     // 16 x 16 thread grid
    const int rowBase = blockIdx.y * 128, colBase = blockIdx.x * 128;
    float acc[8][8] = {};

    for (int k0 = 0; k0 < K; k0 += 16) {
        // load A tile 128x16 (transposed into As[k][m]); 2 float4 per thread
        #pragma unroll
        for (int l = 0; l < 2; l++) {
            int idx = tid + l * 256;            // 0..511
            int m = idx >> 2, kq = (idx & 3) * 4;
            int r = rowBase + m;
            float4 v = make_float4(0.f, 0.f, 0.f, 0.f);
            if (r < M) v = *reinterpret_cast<const float4*>(
                            A + (size_t)r * K + k0 + kq);
            As[kq + 0][m] = v.x; As[kq + 1][m] = v.y;
            As[kq + 2][m] = v.z; As[kq + 3][m] = v.w;
        }
        // load B tile 16x128; 2 float4 per thread
        #pragma unroll
        for (int l = 0; l < 2; l++) {
            int idx = tid + l * 256;
            int kr = idx >> 5, c4 = (idx & 31) * 4;
            float4 v = *reinterpret_cast<const float4*>(
                        B + (size_t)(k0 + kr) * N + colBase + c4);
            *reinterpret_cast<float4*>(&Bs[kr][c4]) = v;
        }
        __syncthreads();
        #pragma unroll
        for (int k = 0; k < 16; k++) {
            float4 a0 = *reinterpret_cast<const float4*>(&As[k][ty * 8]);
            float4 a1 = *reinterpret_cast<const float4*>(&As[k][ty * 8 + 4]);
            float4 b0 = *reinterpret_cast<const float4*>(&Bs[k][tx * 8]);
            float4 b1 = *reinterpret_cast<const float4*>(&Bs[k][tx * 8 + 4]);
            float av[8] = {a0.x, a0.y, a0.z, a0.w, a1.x, a1.y, a1.z, a1.w};
            float bv[8] = {b0.x, b0.y, b0.z, b0.w, b1.x, b1.y, b1.z, b1.w};
            #pragma unroll
            for (int i = 0; i < 8; i++)
                #pragma unroll
                for (int j = 0; j < 8; j++)
                    acc[i][j] = fmaf(av[i], bv[j], acc[i][j]);
        }
        __syncthreads();
    }

    // epilogue
    #pragma unroll
    for (int i = 0; i < 8; i++) {
        int r = rowBase + ty * 8 + i;
        if (r >= M) continue;
        if (MODE == 0) {
            float dc = g_dinv1[r]; dc *= dc;
            #pragma unroll
            for (int jj = 0; jj < 2; jj++) {
                float4 v = make_float4(acc[i][jj*4+0], acc[i][jj*4+1],
                                       acc[i][jj*4+2], acc[i][jj*4+3]);
                size_t off = (size_t)r * N + colBase + tx * 8 + jj * 4;
                *reinterpret_cast<float4*>(g_xw + off) = v;
                float4 h = make_float4(dc*v.x, dc*v.y, dc*v.z, dc*v.w);
                *reinterpret_cast<float4*>(g_H + off) = h;
            }
        } else {
            #pragma unroll
            for (int jj = 0; jj < 2; jj++) {
                int c = colBase + tx * 8 + jj * 4;
                float4 v;
                v.x = tanhf(acc[i][jj*4+0] + g_bias2[c+0]);
                v.y = tanhf(acc[i][jj*4+1] + g_bias2[c+1]);
                v.z = tanhf(acc[i][jj*4+2] + g_bias2[c+2]);
                v.w = tanhf(acc[i][jj*4+3] + g_bias2[c+3]);
                *reinterpret_cast<float4*>(g_abs + (size_t)r * N + c) = v;
            }
        }
    }
}

// ---------------- GCN edge scatter: H[c] += dinv1[r]*dinv1[c] * xw[r] --------
// One warp per edge; each lane handles 8 columns (stride 32) with scalar REDs.
__global__ void k_scatter1(const int* __restrict__ row,
                           const int* __restrict__ col) {
    int wid  = (blockIdx.x * blockDim.x + threadIdx.x) >> 5;
    int lane = threadIdx.x & 31;
    if (wid >= NE) return;
    int r = row[wid], c = col[wid];
    float coef = g_dinv1[r] * g_dinv1[c];
    const float* src = g_xw + (size_t)r * D1;
    float*       dst = g_H  + (size_t)c * D1;
    #pragma unroll
    for (int q = 0; q < 8; q++) {
        int d = lane + q * 32;
        atomicAdd(dst + d, coef * src[d]);
    }
}

// ---------------- column sums of raw H (for embedding) -----------------------
__global__ void k_colsum() {
    const int d = threadIdx.x;                  // 256 threads = one per column
    const int r0 = blockIdx.x * 256;
    const int r1 = min(r0 + 256, NN);
    float part = 0.f;
    for (int n = r0; n < r1; n++) part += g_H[(size_t)n * D1 + d];
    atomicAdd(&g_hsum[d], part);
}

// ---------------- fused GEMM3 + softmax: S = softmax(abs @ fc2_W + fc2_b) ----
// One warp per row; lane k owns output column k (KC = 32).
__global__ void k_gemm3_softmax(const float* __restrict__ W,
                                const float* __restrict__ b) {
    __shared__ float Wsm[D2 * KC];
    __shared__ float bsm[KC];
    __shared__ float rowsm[8][D2];
    const int tid = threadIdx.x;
    for (int i = tid; i < D2 * KC; i += 256) Wsm[i] = W[i];
    if (tid < KC) bsm[tid] = b[tid];
    __syncthreads();
    const int warp = tid >> 5, lane = tid & 31;
    const int r = blockIdx.x * 8 + warp;
    if (r >= NN) return;
    for (int j = lane; j < D2; j += 32) rowsm[warp][j] = g_abs[(size_t)r * D2 + j];
    __syncwarp();
    float acc = bsm[lane];
    #pragma unroll 8
    for (int j = 0; j < D2; j++) acc = fmaf(rowsm[warp][j], Wsm[j * KC + lane], acc);
    float m = acc;
    #pragma unroll
    for (int o = 16; o; o >>= 1) m = fmaxf(m, __shfl_xor_sync(0xffffffffu, m, o));
    float p = expf(acc - m);
    float s = p;
    #pragma unroll
    for (int o = 16; o; o >>= 1) s += __shfl_xor_sync(0xffffffffu, s, o);
    float v = p / s;
    g_S[(size_t)r * KC + lane]  = v;
    g_LS[(size_t)r * KC + lane] = v;   // LS initialized to I*S
}

// ---------------- Laplacian scatter: LS[r] += -(dinv2[r]*dinv2[c]) * S[c] ----
// One thread per (edge, column): 32 columns per edge, coalesced per warp.
__global__ void k_scatter2(const int* __restrict__ row,
                           const int* __restrict__ col) {
    size_t gid = (size_t)blockIdx.x * blockDim.x + threadIdx.x;
    if (gid >= (size_t)NE * KC) return;
    int e = (int)(gid >> 5), k = (int)(gid & 31);
    int r = row[e], c = col[e];
    float wl = -g_dinv2[r] * g_dinv2[c];
    if (wl == 0.f) return;
    float v = g_S[(size_t)c * KC + k];
    atomicAdd(&g_LS[(size_t)r * KC + k], wl * v);
}

// ---------------- new_adj = S^T @ LS  (32x32 block-local reduction) ----------
__global__ void k_newadj() {
    __shared__ float Ssm[32][33];
    __shared__ float Lsm[32][33];
    const int tid = threadIdx.x;                // 1024 threads
    const int i = tid >> 5, j = tid & 31;
    float acc = 0.f;
    const int base = blockIdx.x * 1024;
    for (int t = 0; t < 32; t++) {
        int nn = base + t * 32 + i;
        float sv = 0.f, lv = 0.f;
        if (nn < NN) {
            sv = g_S[(size_t)nn * KC + j];
            lv = g_LS[(size_t)nn * KC + j];
        }
        Ssm[i][j] = sv;
        Lsm[i][j] = lv;
        __syncthreads();
        #pragma unroll
        for (int n = 0; n < 32; n++) acc = fmaf(Ssm[n][i], Lsm[n][j], acc);
        __syncthreads();
    }
    atomicAdd(&g_newadj[i * KC + j], acc);
}

// ---------------- final: penalty + embedding ---------------------------------
__global__ void k_final(float* __restrict__ out, const float* __restrict__ b1) {
    __shared__ float adj[KC * KC];
    __shared__ float diag[KC];
    const int tid = threadIdx.x;                // 256 threads
    for (int idx = tid; idx < KC * KC; idx += 256) adj[idx] = g_newadj[idx];
    __syncthreads();
    if (tid < KC) {
        float rs = 0.f;
        for (int l = 0; l < KC; l++) rs += fabsf(adj[tid * KC + l]);
        diag[tid] = adj[tid * KC + tid] / fmaxf(rs, 1e-12f);
    }
    __syncthreads();
    if (tid < D1)
        out[tid] = (g_hsum[tid] + (float)NN * b1[tid]) * (1.0f / (float)KC);
    if (tid == 0) {
        float pp = 0.f;
        for (int jj = 0; jj < KC; jj++) {
            float d = diag[jj];
            pp += (d - 1.f) * (d - 1.f) + (float)(KC - 1) * d * d;
        }
        out[D1] = pp / (float)(KC * KC);
    }
}

// ---------------- host launcher ----------------------------------------------
extern "C" void kernel_launch(void* const* d_in, const int* in_sizes, int n_in,
                              void* d_out, int out_size) {
    const float* features = (const float*)d_in[0];
    const int*   edges    = (const int*)d_in[1];   // int64 -> int32 by harness
    const float* W1       = (const float*)d_in[2];
    const float* b1       = (const float*)d_in[3];
    const float* fc1W     = (const float*)d_in[4];
    const float* fc1b     = (const float*)d_in[5];
    const float* fc2W     = (const float*)d_in[6];
    const float* fc2b     = (const float*)d_in[7];
    float* out = (float*)d_out;

    const int* row = edges;        // edges[0, :]
    const int* col = edges + NE;   // edges[1, :]

    // 1. degree + norm precompute (+ bias2)
    k_init<<<(NN + 255) / 256, 256>>>();
    k_count<<<(NE + 255) / 256, 256>>>(row, col);
    k_dinv<<<(NN + 255) / 256, 256>>>();
    k_bias2<<<1, D2>>>(b1, fc1W, fc1b);

    // 2. g_xw = features @ W1; g_H = dinv1^2 * g_xw (fused epilogue)
    {
        dim3 grid(D1 / 128, (NN + 127) / 128);
        k_gemm<0><<<grid, 256>>>(features, W1, NN, D1, F_IN);
    }

    // 3. GCN edge aggregation into g_H, then column sums
    {
        size_t threads = (size_t)NE * 32;
        k_scatter1<<<(unsigned)((threads + 255) / 256), 256>>>(row, col);
    }
    k_colsum<<<(NN + 255) / 256, 256>>>();

    // 4. g_abs = tanh(g_H @ fc1_W + bias2)   [50000,256]@[256,128]
    {
        dim3 grid(D2 / 128, (NN + 127) / 128);
        k_gemm<1><<<grid, 256>>>(nullptr, fc1W, NN, D2, D1);
    }

    // 5. S = softmax(abs @ fc2_W + fc2_b), LS = S
    k_gemm3_softmax<<<(NN + 7) / 8, 256>>>(fc2W, fc2b);

    // 6. LS += scatter of Laplacian off-diagonals
    {
        size_t threads = (size_t)NE * KC;
        k_scatter2<<<(unsigned)((threads + 255) / 256), 256>>>(row, col);
    }

    // 7. new_adj = S^T @ LS
    k_newadj<<<(NN + 1023) / 1024, 1024>>>();

    // 8. outputs
    k_final<<<1, 256>>>(out, b1);
}

// round 11
// speedup vs baseline: 1.5588x; 1.3257x over previous
#include <cuda_runtime.h>
#include <cuda_bf16.h>
#include <math.h>

// Problem constants (fixed by the dataset)
constexpr int NN   = 50000;   // nodes
constexpr int NE   = 800000;  // edges
constexpr int F_IN = 128;
constexpr int D1   = 256;
constexpr int D2   = 128;
constexpr int KC   = 32;      // clusters

// ---------------- scratch (static device globals; no allocation) -------------
__device__ float g_xw[(size_t)NN * D1];     // features @ W1
__device__ float g_H[(size_t)NN * D1];      // GCN output (raw, no +b1)
__device__ float g_abs[(size_t)NN * D2];    // tanh(H@fc1_W+bias2)
__device__ float g_S[(size_t)NN * KC];      // softmax assignments
__device__ float g_LS[(size_t)NN * KC];     // L @ S
__device__ int   g_deg1[NN];                // in-degree + 1 (GCN norm)
__device__ int   g_deg2[NN];                // out-degree (Laplacian)
__device__ float g_dinv1[NN];
__device__ float g_dinv2[NN];
__device__ int   g_start1[NN];              // CSR (incoming, keyed by col)
__device__ int   g_start2[NN];              // CSR (outgoing, keyed by row)
__device__ int   g_cur1[NN];
__device__ int   g_cur2[NN];
__device__ int   g_adj1[NE];                // sources of incoming edges
__device__ int   g_adj2[NE];                // targets of outgoing edges
__device__ float g_newadj[KC * KC];
__device__ float g_hsum[D1];
__device__ float g_bias2[D2];               // fc1_b + b1 @ fc1_W

// ---------------- init: degrees, accumulators --------------------------------
__global__ void k_init() {
    int i = blockIdx.x * blockDim.x + threadIdx.x;
    if (i < NN) { g_deg1[i] = 1; g_deg2[i] = 0; }
    if (i < KC * KC) g_newadj[i] = 0.f;
    if (i < D1) g_hsum[i] = 0.f;
}

__global__ void k_count(const int* __restrict__ row,
                        const int* __restrict__ col) {
    int e = blockIdx.x * blockDim.x + threadIdx.x;
    if (e >= NE) return;
    atomicAdd(&g_deg1[col[e]], 1);
    atomicAdd(&g_deg2[row[e]], 1);
}

__global__ void k_dinv() {
    int i = blockIdx.x * blockDim.x + threadIdx.x;
    if (i >= NN) return;
    g_dinv1[i] = rsqrtf((float)g_deg1[i]);              // deg1 >= 1 always
    int d2 = g_deg2[i];
    g_dinv2[i] = d2 > 0 ? rsqrtf((float)d2) : 0.f;
}

// ---------------- exclusive scan of degrees -> CSR starts --------------------
// block 0: in-degree (g_deg1 - 1) -> g_start1/g_cur1
// block 1: out-degree (g_deg2)    -> g_start2/g_cur2
__global__ void k_scan() {
    __shared__ int sums[1024];
    const int tid = threadIdx.x;
    const int which = blockIdx.x;
    const int CH = (NN + 1023) / 1024;      // 49
    const int base = tid * CH;
    int local = 0;
    for (int i = 0; i < CH; i++) {
        int idx = base + i;
        if (idx < NN)
            local += (which == 0) ? (g_deg1[idx] - 1) : g_deg2[idx];
    }
    sums[tid] = local;
    __syncthreads();
    // Hillis-Steele inclusive scan
    for (int off = 1; off < 1024; off <<= 1) {
        int v = (tid >= off) ? sums[tid - off] : 0;
        __syncthreads();
        sums[tid] += v;
        __syncthreads();
    }
    int running = (tid > 0) ? sums[tid - 1] : 0;   // exclusive prefix
    for (int i = 0; i < CH; i++) {
        int idx = base + i;
        if (idx < NN) {
            if (which == 0) { g_start1[idx] = running; g_cur1[idx] = running; }
            else            { g_start2[idx] = running; g_cur2[idx] = running; }
            running += (which == 0) ? (g_deg1[idx] - 1) : g_deg2[idx];
        }
    }
}

// ---------------- fill CSR adjacency lists -----------------------------------
__global__ void k_fill(const int* __restrict__ row,
                       const int* __restrict__ col) {
    int e = blockIdx.x * blockDim.x + threadIdx.x;
    if (e >= NE) return;
    int r = row[e], c = col[e];
    int p1 = atomicAdd(&g_cur1[c], 1); g_adj1[p1] = r;   // incoming to c
    int p2 = atomicAdd(&g_cur2[r], 1); g_adj2[p2] = c;   // outgoing from r
}

// ---------------- bias2[j] = fc1_b[j] + sum_k b1[k] * fc1_W[k][j] ------------
// one block per output column j, 256 threads reduce over k.
__global__ void k_bias2(const float* __restrict__ b1,
                        const float* __restrict__ fc1W,
                        const float* __restrict__ fc1b) {
    __shared__ float red[256];
    const int j = blockIdx.x, k = threadIdx.x;
    red[k] = b1[k] * fc1W[(size_t)k * D2 + j];
    __syncthreads();
    for (int off = 128; off > 0; off >>= 1) {
        if (k < off) red[k] += red[k + off];
        __syncthreads();
    }
    if (k == 0) g_bias2[j] = red[0] + fc1b[j];
}

// ---------------- 128x128x16 SGEMM, 256 threads, 8x8 microtile ---------------
// MODE 0: g_xw  = A@B                       (A=features, B=W1,   N=256, K=128)
// MODE 1: g_abs = tanh(g_H@B + g_bias2[c])  (B=fc1_W,            N=128, K=256)
template<int MODE>
__global__ void k_gemm(const float* __restrict__ Aparam,
                       const float* __restrict__ B,
                       int M, int N, int K) {
    const float* A = (MODE == 0) ? Aparam : g_H;
    __shared__ float As[16][136];   // padded: conflict-free transposed stores
    __shared__ float Bs[16][128];
    const int tid = threadIdx.x;
    const int tx = tid & 15, ty = tid >> 4;     // 16 x 16 thread grid
    const int rowBase = blockIdx.y * 128, colBase = blockIdx.x * 128;
    float acc[8][8] = {};

    for (int k0 = 0; k0 < K; k0 += 16) {
        #pragma unroll
        for (int l = 0; l < 2; l++) {
            int idx = tid + l * 256;            // 0..511
            int m = idx >> 2, kq = (idx & 3) * 4;
            int r = rowBase + m;
            float4 v = make_float4(0.f, 0.f, 0.f, 0.f);
            if (r < M) v = *reinterpret_cast<const float4*>(
                            A + (size_t)r * K + k0 + kq);
            As[kq + 0][m] = v.x; As[kq + 1][m] = v.y;
            As[kq + 2][m] = v.z; As[kq + 3][m] = v.w;
        }
        #pragma unroll
        for (int l = 0; l < 2; l++) {
            int idx = tid + l * 256;
            int kr = idx >> 5, c4 = (idx & 31) * 4;
            float4 v = *reinterpret_cast<const float4*>(
                        B + (size_t)(k0 + kr) * N + colBase + c4);
            *reinterpret_cast<float4*>(&Bs[kr][c4]) = v;
        }
        __syncthreads();
        #pragma unroll
        for (int k = 0; k < 16; k++) {
            float4 a0 = *reinterpret_cast<const float4*>(&As[k][ty * 8]);
            float4 a1 = *reinterpret_cast<const float4*>(&As[k][ty * 8 + 4]);
            float4 b0 = *reinterpret_cast<const float4*>(&Bs[k][tx * 8]);
            float4 b1 = *reinterpret_cast<const float4*>(&Bs[k][tx * 8 + 4]);
            float av[8] = {a0.x, a0.y, a0.z, a0.w, a1.x, a1.y, a1.z, a1.w};
            float bv[8] = {b0.x, b0.y, b0.z, b0.w, b1.x, b1.y, b1.z, b1.w};
            #pragma unroll
            for (int i = 0; i < 8; i++)
                #pragma unroll
                for (int j = 0; j < 8; j++)
                    acc[i][j] = fmaf(av[i], bv[j], acc[i][j]);
        }
        __syncthreads();
    }

    #pragma unroll
    for (int i = 0; i < 8; i++) {
        int r = rowBase + ty * 8 + i;
        if (r >= M) continue;
        #pragma unroll
        for (int jj = 0; jj < 2; jj++) {
            int c = colBase + tx * 8 + jj * 4;
            size_t off = (size_t)r * N + c;
            if (MODE == 0) {
                float4 v = make_float4(acc[i][jj*4+0], acc[i][jj*4+1],
                                       acc[i][jj*4+2], acc[i][jj*4+3]);
                *reinterpret_cast<float4*>(g_xw + off) = v;
            } else {
                float4 v;
                v.x = tanhf(acc[i][jj*4+0] + g_bias2[c+0]);
                v.y = tanhf(acc[i][jj*4+1] + g_bias2[c+1]);
                v.z = tanhf(acc[i][jj*4+2] + g_bias2[c+2]);
                v.w = tanhf(acc[i][jj*4+3] + g_bias2[c+3]);
                *reinterpret_cast<float4*>(g_abs + off) = v;
            }
        }
    }
}

// ---------------- GCN gather: H[n] = dinv1[n]^2*xw[n] + sum_in coef*xw[r] ----
// One warp per node (8 warps/block, NN = 6250*8 exactly). Also accumulates
// column sums for the graph embedding (smem + global atomics).
__global__ void k_gather1() {
    __shared__ float cs[D1];
    const int tid  = threadIdx.x;
    const int warp = tid >> 5, lane = tid & 31;
    const int node = blockIdx.x * 8 + warp;
    cs[tid] = 0.f;
    __syncthreads();

    const float dcn = g_dinv1[node];
    const float* self = g_xw + (size_t)node * D1;
    float acc[8];
    #pragma unroll
    for (int q = 0; q < 8; q++) acc[q] = dcn * dcn * self[lane + q * 32];

    const int s   = g_start1[node];
    const int cnt = g_deg1[node] - 1;
    for (int i = 0; i < cnt; i++) {
        int r = g_adj1[s + i];
        float coef = g_dinv1[r] * dcn;
        const float* src = g_xw + (size_t)r * D1;
        #pragma unroll
        for (int q = 0; q < 8; q++)
            acc[q] = fmaf(coef, src[lane + q * 32], acc[q]);
    }
    float* dst = g_H + (size_t)node * D1;
    #pragma unroll
    for (int q = 0; q < 8; q++) {
        dst[lane + q * 32] = acc[q];
        atomicAdd(&cs[lane + q * 32], acc[q]);
    }
    __syncthreads();
    atomicAdd(&g_hsum[tid], cs[tid]);
}

// ---------------- fused GEMM3 + softmax: S = softmax(abs @ fc2_W + fc2_b) ----
// One warp per row; lane k owns output column k (KC = 32).
__global__ void k_gemm3_softmax(const float* __restrict__ W,
                                const float* __restrict__ b) {
    __shared__ float Wsm[D2 * KC];
    __shared__ float bsm[KC];
    __shared__ float rowsm[8][D2];
    const int tid = threadIdx.x;
    for (int i = tid; i < D2 * KC; i += 256) Wsm[i] = W[i];
    if (tid < KC) bsm[tid] = b[tid];
    __syncthreads();
    const int warp = tid >> 5, lane = tid & 31;
    const int r = blockIdx.x * 8 + warp;
    if (r >= NN) return;
    for (int j = lane; j < D2; j += 32) rowsm[warp][j] = g_abs[(size_t)r * D2 + j];
    __syncwarp();
    float acc = bsm[lane];
    #pragma unroll 8
    for (int j = 0; j < D2; j++) acc = fmaf(rowsm[warp][j], Wsm[j * KC + lane], acc);
    float m = acc;
    #pragma unroll
    for (int o = 16; o; o >>= 1) m = fmaxf(m, __shfl_xor_sync(0xffffffffu, m, o));
    float p = expf(acc - m);
    float s = p;
    #pragma unroll
    for (int o = 16; o; o >>= 1) s += __shfl_xor_sync(0xffffffffu, s, o);
    g_S[(size_t)r * KC + lane] = p / s;
}

// ---------------- Laplacian gather: LS[n] = S[n] - sum_out dd * S[c] ---------
// One warp per node; lane = cluster column.
__global__ void k_gather2() {
    const int tid  = threadIdx.x;
    const int warp = tid >> 5, lane = tid & 31;
    const int node = blockIdx.x * 8 + warp;
    const float dcn = g_dinv2[node];
    float acc = g_S[(size_t)node * KC + lane];
    const int s   = g_start2[node];
    const int cnt = g_deg2[node];
    for (int i = 0; i < cnt; i++) {
        int c = g_adj2[s + i];
        float wl = dcn * g_dinv2[c];
        acc = fmaf(-wl, g_S[(size_t)c * KC + lane], acc);
    }
    g_LS[(size_t)node * KC + lane] = acc;
}

// ---------------- new_adj = S^T @ LS  (32x32 block-local reduction) ----------
__global__ void k_newadj() {
    __shared__ float Ssm[32][33];
    __shared__ float Lsm[32][33];
    const int tid = threadIdx.x;                // 1024 threads
    const int i = tid >> 5, j = tid & 31;
    float acc = 0.f;
    const int base = blockIdx.x * 1024;
    for (int t = 0; t < 32; t++) {
        int nn = base + t * 32 + i;
        float sv = 0.f, lv = 0.f;
        if (nn < NN) {
            sv = g_S[(size_t)nn * KC + j];
            lv = g_LS[(size_t)nn * KC + j];
        }
        Ssm[i][j] = sv;
        Lsm[i][j] = lv;
        __syncthreads();
        #pragma unroll
        for (int n = 0; n < 32; n++) acc = fmaf(Ssm[n][i], Lsm[n][j], acc);
        __syncthreads();
    }
    atomicAdd(&g_newadj[i * KC + j], acc);
}

// ---------------- final: penalty + embedding ---------------------------------
__global__ void k_final(float* __restrict__ out, const float* __restrict__ b1) {
    __shared__ float adj[KC * KC];
    __shared__ float diag[KC];
    const int tid = threadIdx.x;                // 256 threads
    for (int idx = tid; idx < KC * KC; idx += 256) adj[idx] = g_newadj[idx];
    __syncthreads();
    if (tid < KC) {
        float rs = 0.f;
        for (int l = 0; l < KC; l++) rs += fabsf(adj[tid * KC + l]);
        diag[tid] = adj[tid * KC + tid] / fmaxf(rs, 1e-12f);
    }
    __syncthreads();
    if (tid < D1)
        out[tid] = (g_hsum[tid] + (float)NN * b1[tid]) * (1.0f / (float)KC);
    if (tid == 0) {
        float pp = 0.f;
        for (int jj = 0; jj < KC; jj++) {
            float d = diag[jj];
            pp += (d - 1.f) * (d - 1.f) + (float)(KC - 1) * d * d;
        }
        out[D1] = pp / (float)(KC * KC);
    }
}

// ---------------- host launcher ----------------------------------------------
extern "C" void kernel_launch(void* const* d_in, const int* in_sizes, int n_in,
                              void* d_out, int out_size) {
    const float* features = (const float*)d_in[0];
    const int*   edges    = (const int*)d_in[1];   // int64 -> int32 by harness
    const float* W1       = (const float*)d_in[2];
    const float* b1       = (const float*)d_in[3];
    const float* fc1W     = (const float*)d_in[4];
    const float* fc1b     = (const float*)d_in[5];
    const float* fc2W     = (const float*)d_in[6];
    const float* fc2b     = (const float*)d_in[7];
    float* out = (float*)d_out;

    const int* row = edges;        // edges[0, :]
    const int* col = edges + NE;   // edges[1, :]

    // 1. degrees, norms, CSR build, bias2
    k_init<<<(NN + 255) / 256, 256>>>();
    k_count<<<(NE + 255) / 256, 256>>>(row, col);
    k_dinv<<<(NN + 255) / 256, 256>>>();
    k_scan<<<2, 1024>>>();
    k_fill<<<(NE + 255) / 256, 256>>>(row, col);
    k_bias2<<<D2, 256>>>(b1, fc1W, fc1b);

    // 2. g_xw = features @ W1
    {
        dim3 grid(D1 / 128, (NN + 127) / 128);
        k_gemm<0><<<grid, 256>>>(features, W1, NN, D1, F_IN);
    }

    // 3. GCN aggregation (gather, no atastomics) + column sums
    k_gather1<<<NN / 8, 256>>>();

    // 4. g_abs = tanh(g_H @ fc1_W + bias2)
    {
        dim3 grid(D2 / 128, (NN + 127) / 128);
        k_gemm<1><<<grid, 256>>>(nullptr, fc1W, NN, D2, D1);
    }

    // 5. S = softmax(abs @ fc2_W + fc2_b)
    k_gemm3_softmax<<<(NN + 7) / 8, 256>>>(fc2W, fc2b);

    // 6. LS = S - Laplacian gather
    k_gather2<<<NN / 8, 256>>>();

    // 7. new_adj = S^T @ LS
    k_newadj<<<(NN + 1023) / 1024, 1024>>>();

    // 8. outputs
    k_final<<<1, 256>>>(out, b1);
}

// round 12
// speedup vs baseline: 1.8974x; 1.2172x over previous
#include <cuda_runtime.h>
#include <cuda_bf16.h>
#include <math.h>

// Problem constants (fixed by the dataset)
constexpr int NN   = 50000;   // nodes
constexpr int NE   = 800000;  // edges
constexpr int F_IN = 128;
constexpr int D1   = 256;
constexpr int D2   = 128;
constexpr int KC   = 32;      // clusters

// ---------------- scratch (static device globals; no allocation) -------------
__device__ float g_xw[(size_t)NN * D1];     // features @ W1
__device__ float g_H[(size_t)NN * D1];      // GCN output (raw, no +b1)
__device__ float g_abs[(size_t)NN * D2];    // tanh(H@fc1_W+bias2)
__device__ float g_S[(size_t)NN * KC];      // softmax assignments
__device__ float g_LS[(size_t)NN * KC];     // L @ S
__device__ int   g_deg1[NN];                // in-degree + 1 (GCN norm)
__device__ int   g_deg2[NN];                // out-degree (Laplacian)
__device__ float g_dinv1[NN];
__device__ float g_dinv2[NN];
__device__ int   g_start1[NN];              // CSR (incoming, keyed by col)
__device__ int   g_start2[NN];              // CSR (outgoing, keyed by row)
__device__ int   g_cur1[NN];
__device__ int   g_cur2[NN];
__device__ int   g_adj1[NE];                // sources of incoming edges
__device__ int   g_adj2[NE];                // targets of outgoing edges
__device__ int   g_total1, g_total2;        // range-allocation counters
__device__ float g_newadj[KC * KC];
__device__ float g_hsum[D1];
__device__ float g_bias2[D2];               // fc1_b + b1 @ fc1_W

// ---------------- init: degrees, accumulators --------------------------------
__global__ void k_init() {
    int i = blockIdx.x * blockDim.x + threadIdx.x;
    if (i < NN) { g_deg1[i] = 1; g_deg2[i] = 0; }
    if (i < KC * KC) g_newadj[i] = 0.f;
    if (i < D1) g_hsum[i] = 0.f;
    if (i == 0) { g_total1 = 0; g_total2 = 0; }
}

__global__ void k_count(const int* __restrict__ row,
                        const int* __restrict__ col) {
    int e = blockIdx.x * blockDim.x + threadIdx.x;
    if (e >= NE) return;
    atomicAdd(&g_deg1[col[e]], 1);
    atomicAdd(&g_deg2[row[e]], 1);
}

__global__ void k_dinv() {
    int i = blockIdx.x * blockDim.x + threadIdx.x;
    if (i >= NN) return;
    g_dinv1[i] = rsqrtf((float)g_deg1[i]);              // deg1 >= 1 always
    int d2 = g_deg2[i];
    g_dinv2[i] = d2 > 0 ? rsqrtf((float)d2) : 0.f;
}

// ---------------- CSR range allocation (order-free "scan") -------------------
// Each warp: shfl inclusive scan of degrees, ONE atomicAdd per counter to grab
// a contiguous base, then per-lane offsets. Ranges are disjoint + contiguous
// per node, which is all the gather kernels need (order is irrelevant).
__global__ void k_offsets() {
    int i = blockIdx.x * blockDim.x + threadIdx.x;
    int lane = threadIdx.x & 31;
    bool valid = i < NN;
    int d1 = valid ? (g_deg1[i] - 1) : 0;
    int d2 = valid ? g_deg2[i] : 0;
    int s1 = d1, s2 = d2;
    #pragma unroll
    for (int o = 1; o < 32; o <<= 1) {
        int t1 = __shfl_up_sync(0xffffffffu, s1, o);
        int t2 = __shfl_up_sync(0xffffffffu, s2, o);
        if (lane >= o) { s1 += t1; s2 += t2; }
    }
    int base1 = 0, base2 = 0;
    if (lane == 31) {
        base1 = atomicAdd(&g_total1, s1);
        base2 = atomicAdd(&g_total2, s2);
    }
    base1 = __shfl_sync(0xffffffffu, base1, 31);
    base2 = __shfl_sync(0xffffffffu, base2, 31);
    if (valid) {
        int p1 = base1 + s1 - d1;
        int p2 = base2 + s2 - d2;
        g_start1[i] = p1; g_cur1[i] = p1;
        g_start2[i] = p2; g_cur2[i] = p2;
    }
}

// ---------------- fill CSR adjacency lists -----------------------------------
__global__ void k_fill(const int* __restrict__ row,
                       const int* __restrict__ col) {
    int e = blockIdx.x * blockDim.x + threadIdx.x;
    if (e >= NE) return;
    int r = row[e], c = col[e];
    int p1 = atomicAdd(&g_cur1[c], 1); g_adj1[p1] = r;   // incoming to c
    int p2 = atomicAdd(&g_cur2[r], 1); g_adj2[p2] = c;   // outgoing from r
}

// ---------------- bias2[j] = fc1_b[j] + sum_k b1[k] * fc1_W[k][j] ------------
// one block per output column j, 256 threads reduce over k.
__global__ void k_bias2(const float* __restrict__ b1,
                        const float* __restrict__ fc1W,
                        const float* __restrict__ fc1b) {
    __shared__ float red[256];
    const int j = blockIdx.x, k = threadIdx.x;
    red[k] = b1[k] * fc1W[(size_t)k * D2 + j];
    __syncthreads();
    for (int off = 128; off > 0; off >>= 1) {
        if (k < off) red[k] += red[k + off];
        __syncthreads();
    }
    if (k == 0) g_bias2[j] = red[0] + fc1b[j];
}

// ---------------- 128x128x16 SGEMM, 256 threads, 8x8 microtile ---------------
// MODE 0: g_xw  = A@B                       (A=features, B=W1,   N=256, K=128)
// MODE 1: g_abs = tanh(g_H@B + g_bias2[c])  (B=fc1_W,            N=128, K=256)
template<int MODE>
__global__ void k_gemm(const float* __restrict__ Aparam,
                       const float* __restrict__ B,
                       int M, int N, int K) {
    const float* A = (MODE == 0) ? Aparam : g_H;
    __shared__ float As[16][136];   // padded: conflict-free transposed stores
    __shared__ float Bs[16][128];
    const int tid = threadIdx.x;
    const int tx = tid & 15, ty = tid >> 4;     // 16 x 16 thread grid
    const int rowBase = blockIdx.y * 128, colBase = blockIdx.x * 128;
    float acc[8][8] = {};

    for (int k0 = 0; k0 < K; k0 += 16) {
        #pragma unroll
        for (int l = 0; l < 2; l++) {
            int idx = tid + l * 256;            // 0..511
            int m = idx >> 2, kq = (idx & 3) * 4;
            int r = rowBase + m;
            float4 v = make_float4(0.f, 0.f, 0.f, 0.f);
            if (r < M) v = *reinterpret_cast<const float4*>(
                            A + (size_t)r * K + k0 + kq);
            As[kq + 0][m] = v.x; As[kq + 1][m] = v.y;
            As[kq + 2][m] = v.z; As[kq + 3][m] = v.w;
        }
        #pragma unroll
        for (int l = 0; l < 2; l++) {
            int idx = tid + l * 256;
            int kr = idx >> 5, c4 = (idx & 31) * 4;
            float4 v = *reinterpret_cast<const float4*>(
                        B + (size_t)(k0 + kr) * N + colBase + c4);
            *reinterpret_cast<float4*>(&Bs[kr][c4]) = v;
        }
        __syncthreads();
        #pragma unroll
        for (int k = 0; k < 16; k++) {
            float4 a0 = *reinterpret_cast<const float4*>(&As[k][ty * 8]);
            float4 a1 = *reinterpret_cast<const float4*>(&As[k][ty * 8 + 4]);
            float4 b0 = *reinterpret_cast<const float4*>(&Bs[k][tx * 8]);
            float4 b1 = *reinterpret_cast<const float4*>(&Bs[k][tx * 8 + 4]);
            float av[8] = {a0.x, a0.y, a0.z, a0.w, a1.x, a1.y, a1.z, a1.w};
            float bv[8] = {b0.x, b0.y, b0.z, b0.w, b1.x, b1.y, b1.z, b1.w};
            #pragma unroll
            for (int i = 0; i < 8; i++)
                #pragma unroll
                for (int j = 0; j < 8; j++)
                    acc[i][j] = fmaf(av[i], bv[j], acc[i][j]);
        }
        __syncthreads();
    }

    #pragma unroll
    for (int i = 0; i < 8; i++) {
        int r = rowBase + ty * 8 + i;
        if (r >= M) continue;
        #pragma unroll
        for (int jj = 0; jj < 2; jj++) {
            int c = colBase + tx * 8 + jj * 4;
            size_t off = (size_t)r * N + c;
            if (MODE == 0) {
                float4 v = make_float4(acc[i][jj*4+0], acc[i][jj*4+1],
                                       acc[i][jj*4+2], acc[i][jj*4+3]);
                *reinterpret_cast<float4*>(g_xw + off) = v;
            } else {
                float4 v;
                v.x = tanhf(acc[i][jj*4+0] + g_bias2[c+0]);
                v.y = tanhf(acc[i][jj*4+1] + g_bias2[c+1]);
                v.z = tanhf(acc[i][jj*4+2] + g_bias2[c+2]);
                v.w = tanhf(acc[i][jj*4+3] + g_bias2[c+3]);
                *reinterpret_cast<float4*>(g_abs + off) = v;
            }
        }
    }
}

// ---------------- GCN gather: H[n] = dinv1[n]^2*xw[n] + sum_in coef*xw[r] ----
// One warp per node (8 warps/block, NN = 6250*8 exactly). Also accumulates
// column sums for the graph embedding (smem + global atomics).
__global__ void k_gather1() {
    __shared__ float cs[D1];
    const int tid  = threadIdx.x;
    const int warp = tid >> 5, lane = tid & 31;
    const int node = blockIdx.x * 8 + warp;
    cs[tid] = 0.f;
    __syncthreads();

    const float dcn = g_dinv1[node];
    const float* self = g_xw + (size_t)node * D1;
    float acc[8];
    #pragma unroll
    for (int q = 0; q < 8; q++) acc[q] = dcn * dcn * self[lane + q * 32];

    const int s   = g_start1[node];
    const int cnt = g_deg1[node] - 1;
    for (int i = 0; i < cnt; i++) {
        int r = g_adj1[s + i];
        float coef = g_dinv1[r] * dcn;
        const float* src = g_xw + (size_t)r * D1;
        #pragma unroll
        for (int q = 0; q < 8; q++)
            acc[q] = fmaf(coef, src[lane + q * 32], acc[q]);
    }
    float* dst = g_H + (size_t)node * D1;
    #pragma unroll
    for (int q = 0; q < 8; q++) {
        dst[lane + q * 32] = acc[q];
        atomicAdd(&cs[lane + q * 32], acc[q]);
    }
    __syncthreads();
    atomicAdd(&g_hsum[tid], cs[tid]);
}

// ---------------- fused GEMM3 + softmax: S = softmax(abs @ fc2_W + fc2_b) ----
// One warp per row; lane k owns output column k (KC = 32).
__global__ void k_gemm3_softmax(const float* __restrict__ W,
                                const float* __restrict__ b) {
    __shared__ float Wsm[D2 * KC];
    __shared__ float bsm[KC];
    __shared__ float rowsm[8][D2];
    const int tid = threadIdx.x;
    for (int i = tid; i < D2 * KC; i += 256) Wsm[i] = W[i];
    if (tid < KC) bsm[tid] = b[tid];
    __syncthreads();
    const int warp = tid >> 5, lane = tid & 31;
    const int r = blockIdx.x * 8 + warp;
    if (r >= NN) return;
    for (int j = lane; j < D2; j += 32) rowsm[warp][j] = g_abs[(size_t)r * D2 + j];
    __syncwarp();
    float acc = bsm[lane];
    #pragma unroll 8
    for (int j = 0; j < D2; j++) acc = fmaf(rowsm[warp][j], Wsm[j * KC + lane], acc);
    float m = acc;
    #pragma unroll
    for (int o = 16; o; o >>= 1) m = fmaxf(m, __shfl_xor_sync(0xffffffffu, m, o));
    float p = expf(acc - m);
    float s = p;
    #pragma unroll
    for (int o = 16; o; o >>= 1) s += __shfl_xor_sync(0xffffffffu, s, o);
    g_S[(size_t)r * KC + lane] = p / s;
}

// ---------------- Laplacian gather: LS[n] = S[n] - sum_out dd * S[c] ---------
// One warp per node; lane = cluster column.
__global__ void k_gather2() {
    const int tid  = threadIdx.x;
    const int warp = tid >> 5, lane = tid & 31;
    const int node = blockIdx.x * 8 + warp;
    const float dcn = g_dinv2[node];
    float acc = g_S[(size_t)node * KC + lane];
    const int s   = g_start2[node];
    const int cnt = g_deg2[node];
    for (int i = 0; i < cnt; i++) {
        int c = g_adj2[s + i];
        float wl = dcn * g_dinv2[c];
        acc = fmaf(-wl, g_S[(size_t)c * KC + lane], acc);
    }
    g_LS[(size_t)node * KC + lane] = acc;
}

// ---------------- new_adj = S^T @ LS  (32x32 block-local reduction) ----------
__global__ void k_newadj() {
    __shared__ float Ssm[32][33];
    __shared__ float Lsm[32][33];
    const int tid = threadIdx.x;                // 1024 threads
    const int i = tid >> 5, j = tid & 31;
    float acc = 0.f;
    const int base = blockIdx.x * 1024;
    for (int t = 0; t < 32; t++) {
        int nn = base + t * 32 + i;
        float sv = 0.f, lv = 0.f;
        if (nn < NN) {
            sv = g_S[(size_t)nn * KC + j];
            lv = g_LS[(size_t)nn * KC + j];
        }
        Ssm[i][j] = sv;
        Lsm[i][j] = lv;
        __syncthreads();
        #pragma unroll
        for (int n = 0; n < 32; n++) acc = fmaf(Ssm[n][i], Lsm[n][j], acc);
        __syncthreads();
    }
    atomicAdd(&g_newadj[i * KC + j], acc);
}

// ---------------- final: penalty + embedding ---------------------------------
__global__ void k_final(float* __restrict__ out, const float* __restrict__ b1) {
    __shared__ float adj[KC * KC];
    __shared__ float diag[KC];
    const int tid = threadIdx.x;                // 256 threads
    for (int idx = tid; idx < KC * KC; idx += 256) adj[idx] = g_newadj[idx];
    __syncthreads();
    if (tid < KC) {
        float rs = 0.f;
        for (int l = 0; l < KC; l++) rs += fabsf(adj[tid * KC + l]);
        diag[tid] = adj[tid * KC + tid] / fmaxf(rs, 1e-12f);
    }
    __syncthreads();
    if (tid < D1)
        out[tid] = (g_hsum[tid] + (float)NN * b1[tid]) * (1.0f / (float)KC);
    if (tid == 0) {
        float pp = 0.f;
        for (int jj = 0; jj < KC; jj++) {
            float d = diag[jj];
            pp += (d - 1.f) * (d - 1.f) + (float)(KC - 1) * d * d;
        }
        out[D1] = pp / (float)(KC * KC);
    }
}

// ---------------- host launcher ----------------------------------------------
extern "C" void kernel_launch(void* const* d_in, const int* in_sizes, int n_in,
                              void* d_out, int out_size) {
    const float* features = (const float*)d_in[0];
    const int*   edges    = (const int*)d_in[1];   // int64 -> int32 by harness
    const float* W1       = (const float*)d_in[2];
    const float* b1       = (const float*)d_in[3];
    const float* fc1W     = (const float*)d_in[4];
    const float* fc1b     = (const float*)d_in[5];
    const float* fc2W     = (const float*)d_in[6];
    const float* fc2b     = (const float*)d_in[7];
    float* out = (float*)d_out;

    const int* row = edges;        // edges[0, :]
    const int* col = edges + NE;   // edges[1, :]

    // 1. degrees, norms, CSR build, bias2
    k_init<<<(NN + 255) / 256, 256>>>();
    k_count<<<(NE + 255) / 256, 256>>>(row, col);
    k_dinv<<<(NN + 255) / 256, 256>>>();
    k_offsets<<<(NN + 255) / 256, 256>>>();
    k_fill<<<(NE + 255) / 256, 256>>>(row, col);
    k_bias2<<<D2, 256>>>(b1, fc1W, fc1b);

    // 2. g_xw = features @ W1
    {
        dim3 grid(D1 / 128, (NN + 127) / 128);
        k_gemm<0><<<grid, 256>>>(features, W1, NN, D1, F_IN);
    }

    // 3. GCN aggregation (gather, no atomics) + column sums
    k_gather1<<<NN / 8, 256>>>();

    // 4. g_abs = tanh(g_H @ fc1_W + bias2)
    {
        dim3 grid(D2 / 128, (NN + 127) / 128);
        k_gemm<1><<<grid, 256>>>(nullptr, fc1W, NN, D2, D1);
    }

    // 5. S = softmax(abs @ fc2_W + fc2_b)
    k_gemm3_softmax<<<(NN + 7) / 8, 256>>>(fc2W, fc2b);

    // 6. LS = S - Laplacian gather
    k_gather2<<<NN / 8, 256>>>();

    // 7. new_adj = S^T @ LS
    k_newadj<<<(NN + 1023) / 1024, 1024>>>();

    // 8. outputs
    k_final<<<1, 256>>>(out, b1);
}